// round 13
// baseline (speedup 1.0000x reference)
#include <cuda_runtime.h>
#include <cuda_bf16.h>

#define NCOLS 128
#define MAXB  64
#define ROWS_PER_BLOCK 128          // FINE-GRAINED: ~21 block-generations
#define SCATTER_THREADS 256
#define ROWS_PER_WARP 16            // 8 warps x 16 contiguous rows
#define FIN_THREADS 512             // 4 k-slices x 128 output cols

// Persistent scratch (no allocation allowed): [0]=h accumulators, [1]=g.
// Zero-initialized at module load; finalize_kernel re-zeroes after consuming,
// so every kernel_launch entry (incl. graph replays) sees zeroed scratch.
__device__ float g_sums[2][MAXB * NCOLS];
__device__ int   g_cnts[2][MAXB];

__device__ __forceinline__ void l2_prefetch(const void* p) {
    asm volatile("prefetch.global.L2 [%0];" :: "l"(p));
}

// ---------------------------------------------------------------------------
// Streaming segment-sum over BOTH tensors in one grid (two-kernel structure —
// the fused single-kernel variant measured 18us SLOWER twice; reverted).
// Block 0: L2-prefetch of W1/W2/u, overlapped with the stream.
// Blocks 1..gb_h -> chunk of (x_h,batch_h) -> g_sums[0]; else g-tensor.
//
// SMALL BLOCKS ARE THE LEVER THIS ROUND: at 512 rows/block the grid was only
// 2.6 block-generations deep -> ~18% of SM slot-time idle at the tail
// (wave quantization). 128 rows/block -> ~7us blocks, ~21 generations,
// tail waste ~5%.
//
// Each warp owns a CONTIGUOUS 16-row range; lane l owns cols [4l,4l+4).
// Fast path: 8 independent LDG.128 issued before the segment check
// (MLP_p1=8); atomic flushes only at segment boundaries (sorted batch).
// ---------------------------------------------------------------------------
__global__ void __launch_bounds__(SCATTER_THREADS)
scatter_sum_fused_kernel(const float* __restrict__ x_h,
                         const int*   __restrict__ batch_h, int n_h, int gb_h,
                         const float* __restrict__ x_g,
                         const int*   __restrict__ batch_g, int n_g,
                         const float* __restrict__ W1,
                         const float* __restrict__ W2,
                         const float* __restrict__ u) {
    __shared__ int sb[ROWS_PER_BLOCK];

    const int t = threadIdx.x;

    if (blockIdx.x == 0) {
        // Warm L2: W1 [384*128] + W2 [128*128] + u [64*128] floats.
        const float4* w1v = (const float4*)W1;   // 12288 float4
        const float4* w2v = (const float4*)W2;   //  4096 float4
        const float4* uv  = (const float4*)u;    //  2048 float4
        for (int i = t; i < 12288; i += SCATTER_THREADS) l2_prefetch(w1v + i);
        for (int i = t; i < 4096;  i += SCATTER_THREADS) l2_prefetch(w2v + i);
        for (int i = t; i < 2048;  i += SCATTER_THREADS) l2_prefetch(uv + i);
        return;
    }

    int which, blk;
    const float* __restrict__ x;
    const int*   __restrict__ batch;
    int n;
    const int bid = blockIdx.x - 1;
    if (bid < gb_h) {
        which = 0; blk = bid;        x = x_h; batch = batch_h; n = n_h;
    } else {
        which = 1; blk = bid - gb_h; x = x_g; batch = batch_g; n = n_g;
    }

    const int row0 = blk * ROWS_PER_BLOCK;
    int nrows = n - row0;
    if (nrows <= 0) return;
    if (nrows > ROWS_PER_BLOCK) nrows = ROWS_PER_BLOCK;

    if (t < nrows) sb[t] = batch[row0 + t];     // <=128 rows, 256 threads
    __syncthreads();

    const int w    = t >> 5;
    const int lane = t & 31;

    const int start = w * ROWS_PER_WARP;
    if (start >= nrows) return;
    const int end = (start + ROWS_PER_WARP < nrows) ? start + ROWS_PER_WARP
                                                    : nrows;

    float* __restrict__ sums = g_sums[which];
    int*   __restrict__ cnts = g_cnts[which];

    const float4* __restrict__ xv =
        (const float4*)x + (size_t)row0 * (NCOLS / 4) + lane;

    float4 acc = make_float4(0.f, 0.f, 0.f, 0.f);
    int cur = sb[start];
    int cnt = 0;

    int r = start;
    for (; r + 8 <= end; r += 8) {
        // 8 independent wide loads, front-batched (MLP_p1 = 8).
        const float4 v0 = __ldcs(xv + (size_t)(r + 0) * (NCOLS / 4));
        const float4 v1 = __ldcs(xv + (size_t)(r + 1) * (NCOLS / 4));
        const float4 v2 = __ldcs(xv + (size_t)(r + 2) * (NCOLS / 4));
        const float4 v3 = __ldcs(xv + (size_t)(r + 3) * (NCOLS / 4));
        const float4 v4 = __ldcs(xv + (size_t)(r + 4) * (NCOLS / 4));
        const float4 v5 = __ldcs(xv + (size_t)(r + 5) * (NCOLS / 4));
        const float4 v6 = __ldcs(xv + (size_t)(r + 6) * (NCOLS / 4));
        const float4 v7 = __ldcs(xv + (size_t)(r + 7) * (NCOLS / 4));
        const int s0 = sb[r], s7 = sb[r + 7];

        if (s0 == cur && s7 == cur) {           // fast path: sorted batch
            acc.x += ((v0.x + v1.x) + (v2.x + v3.x))
                   + ((v4.x + v5.x) + (v6.x + v7.x));
            acc.y += ((v0.y + v1.y) + (v2.y + v3.y))
                   + ((v4.y + v5.y) + (v6.y + v7.y));
            acc.z += ((v0.z + v1.z) + (v2.z + v3.z))
                   + ((v4.z + v5.z) + (v6.z + v7.z));
            acc.w += ((v0.w + v1.w) + (v2.w + v3.w))
                   + ((v4.w + v5.w) + (v6.w + v7.w));
            cnt += 8;
        } else {                                // boundary: scalar handling
            float4 vv[8] = {v0, v1, v2, v3, v4, v5, v6, v7};
            #pragma unroll
            for (int j = 0; j < 8; j++) {
                const int s = sb[r + j];
                if (s != cur) {
                    atomicAdd(&sums[cur * NCOLS + 4 * lane + 0], acc.x);
                    atomicAdd(&sums[cur * NCOLS + 4 * lane + 1], acc.y);
                    atomicAdd(&sums[cur * NCOLS + 4 * lane + 2], acc.z);
                    atomicAdd(&sums[cur * NCOLS + 4 * lane + 3], acc.w);
                    if (lane == 0 && cnt > 0) atomicAdd(&cnts[cur], cnt);
                    acc = make_float4(0.f, 0.f, 0.f, 0.f);
                    cnt = 0;
                    cur = s;
                }
                acc.x += vv[j].x; acc.y += vv[j].y;
                acc.z += vv[j].z; acc.w += vv[j].w;
                cnt++;
            }
        }
    }
    for (; r < end; r++) {                      // ragged tail rows
        const float4 v = __ldcs(xv + (size_t)r * (NCOLS / 4));
        const int s = sb[r];
        if (s != cur) {
            atomicAdd(&sums[cur * NCOLS + 4 * lane + 0], acc.x);
            atomicAdd(&sums[cur * NCOLS + 4 * lane + 1], acc.y);
            atomicAdd(&sums[cur * NCOLS + 4 * lane + 2], acc.z);
            atomicAdd(&sums[cur * NCOLS + 4 * lane + 3], acc.w);
            if (lane == 0 && cnt > 0) atomicAdd(&cnts[cur], cnt);
            acc = make_float4(0.f, 0.f, 0.f, 0.f);
            cnt = 0;
            cur = s;
        }
        acc.x += v.x; acc.y += v.y; acc.z += v.z; acc.w += v.w;
        cnt++;
    }

    atomicAdd(&sums[cur * NCOLS + 4 * lane + 0], acc.x);
    atomicAdd(&sums[cur * NCOLS + 4 * lane + 1], acc.y);
    atomicAdd(&sums[cur * NCOLS + 4 * lane + 2], acc.z);
    atomicAdd(&sums[cur * NCOLS + 4 * lane + 3], acc.w);
    if (lane == 0 && cnt > 0) atomicAdd(&cnts[cur], cnt);
}

// ---------------------------------------------------------------------------
// Finalize (IDENTICAL to the 88.1us R7 version): k-dim parallelized.
// Block = 512 threads: thread t -> (oc = t & 127, slice = t >> 7).
// Phase 1: 4 slices x 96 k-values of the W1 GEMV, smem tree-sum, leaky_relu.
// Phase 2: 4 slices x 32 k-values for W2.
// Also re-zeroes the consumed scratch (replaces a zero kernel).
// ---------------------------------------------------------------------------
__global__ void __launch_bounds__(FIN_THREADS)
finalize_kernel(const float* __restrict__ u,
                const float* __restrict__ W1, const float* __restrict__ b1,
                const float* __restrict__ W2, const float* __restrict__ b2,
                float* __restrict__ out) {
    __shared__ float row[3 * NCOLS];     // [u | mean_h | mean_g]
    __shared__ float part[4][NCOLS];
    __shared__ float hrow[NCOLS];

    const int b  = blockIdx.x;
    const int t  = threadIdx.x;
    const int oc = t & (NCOLS - 1);
    const int sl = t >> 7;               // 0..3

    if (t < NCOLS) {
        const int ch = g_cnts[0][b];
        const int cg = g_cnts[1][b];
        const float inv_ch = 1.0f / (float)(ch > 1 ? ch : 1);
        const float inv_cg = 1.0f / (float)(cg > 1 ? cg : 1);

        const float sh = g_sums[0][b * NCOLS + t];
        const float sg = g_sums[1][b * NCOLS + t];

        // Re-zero consumed scratch for the next launch/replay.
        g_sums[0][b * NCOLS + t] = 0.0f;
        g_sums[1][b * NCOLS + t] = 0.0f;
        if (t == 0) { g_cnts[0][b] = 0; g_cnts[1][b] = 0; }

        row[t]             = u[b * NCOLS + t];
        row[NCOLS + t]     = sh * inv_ch;
        row[2 * NCOLS + t] = sg * inv_cg;
    }
    __syncthreads();

    // Phase 1: h = leaky_relu(row @ W1 + b1); k split 4 x 96.
    {
        float a0 = 0.f, a1 = 0.f;        // dual accumulators: break fma chain
        const int k0 = sl * 96;
        #pragma unroll 8
        for (int k = 0; k < 96; k += 2) {
            a0 = fmaf(row[k0 + k],     W1[(k0 + k)     * NCOLS + oc], a0);
            a1 = fmaf(row[k0 + k + 1], W1[(k0 + k + 1) * NCOLS + oc], a1);
        }
        part[sl][oc] = a0 + a1;
    }
    __syncthreads();
    if (t < NCOLS) {
        float a = part[0][t] + part[1][t] + part[2][t] + part[3][t] + b1[t];
        hrow[t] = (a > 0.f) ? a : 0.1f * a;   // leaky_relu, slope 0.1
    }
    __syncthreads();

    // Phase 2: out = hrow @ W2 + b2; k split 4 x 32.
    {
        float a0 = 0.f, a1 = 0.f;
        const int k1 = sl * 32;
        #pragma unroll 8
        for (int k = 0; k < 32; k += 2) {
            a0 = fmaf(hrow[k1 + k],     W2[(k1 + k)     * NCOLS + oc], a0);
            a1 = fmaf(hrow[k1 + k + 1], W2[(k1 + k + 1) * NCOLS + oc], a1);
        }
        part[sl][oc] = a0 + a1;
    }
    __syncthreads();
    if (t < NCOLS)
        out[b * NCOLS + t] = part[0][t] + part[1][t] + part[2][t]
                           + part[3][t] + b2[t];
}

// ---------------------------------------------------------------------------
// kernel_launch
// Input order: 0 x_h, 1 x_g, 2 edge_index (unused), 3 edge_attr (unused),
//              4 u, 5 batch_h, 6 batch_g, 7 W1, 8 b1, 9 W2, 10 b2.
// ---------------------------------------------------------------------------
extern "C" void kernel_launch(void* const* d_in, const int* in_sizes, int n_in,
                              void* d_out, int out_size) {
    const float* x_h     = (const float*)d_in[0];
    const float* x_g     = (const float*)d_in[1];
    const float* u       = (const float*)d_in[4];
    const int*   batch_h = (const int*)d_in[5];
    const int*   batch_g = (const int*)d_in[6];
    const float* W1      = (const float*)d_in[7];
    const float* b1      = (const float*)d_in[8];
    const float* W2      = (const float*)d_in[9];
    const float* b2      = (const float*)d_in[10];
    float*       out     = (float*)d_out;

    const int n_h = in_sizes[0] / NCOLS;
    const int n_g = in_sizes[1] / NCOLS;
    const int B   = out_size / NCOLS;   // 64

    const int gb_h = (n_h + ROWS_PER_BLOCK - 1) / ROWS_PER_BLOCK;
    const int gb_g = (n_g + ROWS_PER_BLOCK - 1) / ROWS_PER_BLOCK;
    scatter_sum_fused_kernel<<<gb_h + gb_g + 1, SCATTER_THREADS>>>(
        x_h, batch_h, n_h, gb_h, x_g, batch_g, n_g, W1, W2, u);

    finalize_kernel<<<B, FIN_THREADS>>>(u, W1, b1, W2, b2, out);
}

// round 14
// speedup vs baseline: 2.4191x; 2.4191x over previous
#include <cuda_runtime.h>
#include <cuda_bf16.h>

#define NCOLS 128
#define MAXB  64
#define ROWS_PER_BLOCK 512          // R7-proven: 8 warps x 64 contiguous rows
#define SCATTER_THREADS 256
#define ROWS_PER_WARP 64            // DO NOT SHRINK: flush count = rows/RPW
#define FIN_THREADS 1024            // 8 k-slices x 128 output cols

// Persistent scratch (no allocation allowed): [0]=h accumulators, [1]=g.
// Zero-initialized at module load; finalize_kernel re-zeroes after consuming,
// so every kernel_launch entry (incl. graph replays) sees zeroed scratch.
__device__ float g_sums[2][MAXB * NCOLS];
__device__ int   g_cnts[2][MAXB];

__device__ __forceinline__ void l2_prefetch(const void* p) {
    asm volatile("prefetch.global.L2 [%0];" :: "l"(p));
}

// ---------------------------------------------------------------------------
// Streaming segment-sum over BOTH tensors in one grid. EXACT R7 (88.1us)
// configuration: 512 rows/block, 64 rows/warp (2M boundary atomics — the
// 16-rows/warp variant measured 213us from 8M serialized L2 atomics).
// Block 0: L2-prefetch of W1/W2/u, overlapped with the stream.
// Fast path: 8 independent LDG.128 issued before the segment check
// (MLP_p1=8); atomic flushes only at segment boundaries (sorted batch).
// ---------------------------------------------------------------------------
__global__ void __launch_bounds__(SCATTER_THREADS)
scatter_sum_fused_kernel(const float* __restrict__ x_h,
                         const int*   __restrict__ batch_h, int n_h, int gb_h,
                         const float* __restrict__ x_g,
                         const int*   __restrict__ batch_g, int n_g,
                         const float* __restrict__ W1,
                         const float* __restrict__ W2,
                         const float* __restrict__ u) {
    __shared__ int sb[ROWS_PER_BLOCK];

    const int t = threadIdx.x;

    if (blockIdx.x == 0) {
        // Warm L2: W1 [384*128] + W2 [128*128] + u [64*128] floats.
        const float4* w1v = (const float4*)W1;   // 12288 float4
        const float4* w2v = (const float4*)W2;   //  4096 float4
        const float4* uv  = (const float4*)u;    //  2048 float4
        for (int i = t; i < 12288; i += SCATTER_THREADS) l2_prefetch(w1v + i);
        for (int i = t; i < 4096;  i += SCATTER_THREADS) l2_prefetch(w2v + i);
        for (int i = t; i < 2048;  i += SCATTER_THREADS) l2_prefetch(uv + i);
        return;
    }

    int which, blk;
    const float* __restrict__ x;
    const int*   __restrict__ batch;
    int n;
    const int bid = blockIdx.x - 1;
    if (bid < gb_h) {
        which = 0; blk = bid;        x = x_h; batch = batch_h; n = n_h;
    } else {
        which = 1; blk = bid - gb_h; x = x_g; batch = batch_g; n = n_g;
    }

    const int row0 = blk * ROWS_PER_BLOCK;
    int nrows = n - row0;
    if (nrows <= 0) return;
    if (nrows > ROWS_PER_BLOCK) nrows = ROWS_PER_BLOCK;

    for (int i = t; i < nrows; i += SCATTER_THREADS) sb[i] = batch[row0 + i];
    __syncthreads();

    const int w    = t >> 5;
    const int lane = t & 31;

    const int start = w * ROWS_PER_WARP;
    if (start >= nrows) return;
    const int end = (start + ROWS_PER_WARP < nrows) ? start + ROWS_PER_WARP
                                                    : nrows;

    float* __restrict__ sums = g_sums[which];
    int*   __restrict__ cnts = g_cnts[which];

    const float4* __restrict__ xv =
        (const float4*)x + (size_t)row0 * (NCOLS / 4) + lane;

    float4 acc = make_float4(0.f, 0.f, 0.f, 0.f);
    int cur = sb[start];
    int cnt = 0;

    int r = start;
    for (; r + 8 <= end; r += 8) {
        // 8 independent wide loads, front-batched (MLP_p1 = 8).
        const float4 v0 = __ldcs(xv + (size_t)(r + 0) * (NCOLS / 4));
        const float4 v1 = __ldcs(xv + (size_t)(r + 1) * (NCOLS / 4));
        const float4 v2 = __ldcs(xv + (size_t)(r + 2) * (NCOLS / 4));
        const float4 v3 = __ldcs(xv + (size_t)(r + 3) * (NCOLS / 4));
        const float4 v4 = __ldcs(xv + (size_t)(r + 4) * (NCOLS / 4));
        const float4 v5 = __ldcs(xv + (size_t)(r + 5) * (NCOLS / 4));
        const float4 v6 = __ldcs(xv + (size_t)(r + 6) * (NCOLS / 4));
        const float4 v7 = __ldcs(xv + (size_t)(r + 7) * (NCOLS / 4));
        const int s0 = sb[r], s7 = sb[r + 7];

        if (s0 == cur && s7 == cur) {           // fast path: sorted batch
            acc.x += ((v0.x + v1.x) + (v2.x + v3.x))
                   + ((v4.x + v5.x) + (v6.x + v7.x));
            acc.y += ((v0.y + v1.y) + (v2.y + v3.y))
                   + ((v4.y + v5.y) + (v6.y + v7.y));
            acc.z += ((v0.z + v1.z) + (v2.z + v3.z))
                   + ((v4.z + v5.z) + (v6.z + v7.z));
            acc.w += ((v0.w + v1.w) + (v2.w + v3.w))
                   + ((v4.w + v5.w) + (v6.w + v7.w));
            cnt += 8;
        } else {                                // boundary: scalar handling
            float4 vv[8] = {v0, v1, v2, v3, v4, v5, v6, v7};
            #pragma unroll
            for (int j = 0; j < 8; j++) {
                const int s = sb[r + j];
                if (s != cur) {
                    atomicAdd(&sums[cur * NCOLS + 4 * lane + 0], acc.x);
                    atomicAdd(&sums[cur * NCOLS + 4 * lane + 1], acc.y);
                    atomicAdd(&sums[cur * NCOLS + 4 * lane + 2], acc.z);
                    atomicAdd(&sums[cur * NCOLS + 4 * lane + 3], acc.w);
                    if (lane == 0 && cnt > 0) atomicAdd(&cnts[cur], cnt);
                    acc = make_float4(0.f, 0.f, 0.f, 0.f);
                    cnt = 0;
                    cur = s;
                }
                acc.x += vv[j].x; acc.y += vv[j].y;
                acc.z += vv[j].z; acc.w += vv[j].w;
                cnt++;
            }
        }
    }
    for (; r < end; r++) {                      // ragged tail rows
        const float4 v = __ldcs(xv + (size_t)r * (NCOLS / 4));
        const int s = sb[r];
        if (s != cur) {
            atomicAdd(&sums[cur * NCOLS + 4 * lane + 0], acc.x);
            atomicAdd(&sums[cur * NCOLS + 4 * lane + 1], acc.y);
            atomicAdd(&sums[cur * NCOLS + 4 * lane + 2], acc.z);
            atomicAdd(&sums[cur * NCOLS + 4 * lane + 3], acc.w);
            if (lane == 0 && cnt > 0) atomicAdd(&cnts[cur], cnt);
            acc = make_float4(0.f, 0.f, 0.f, 0.f);
            cnt = 0;
            cur = s;
        }
        acc.x += v.x; acc.y += v.y; acc.z += v.z; acc.w += v.w;
        cnt++;
    }

    atomicAdd(&sums[cur * NCOLS + 4 * lane + 0], acc.x);
    atomicAdd(&sums[cur * NCOLS + 4 * lane + 1], acc.y);
    atomicAdd(&sums[cur * NCOLS + 4 * lane + 2], acc.z);
    atomicAdd(&sums[cur * NCOLS + 4 * lane + 3], acc.w);
    if (lane == 0 && cnt > 0) atomicAdd(&cnts[cur], cnt);
}

// ---------------------------------------------------------------------------
// Finalize v3: 1024 threads — 8 k-slices x 128 output cols.
// Chain length 48 (W1) / 16 (W2) per slice; 32 warps/block for latency
// overlap on the 64 active SMs. Also re-zeroes the consumed scratch.
// ---------------------------------------------------------------------------
__global__ void __launch_bounds__(FIN_THREADS)
finalize_kernel(const float* __restrict__ u,
                const float* __restrict__ W1, const float* __restrict__ b1,
                const float* __restrict__ W2, const float* __restrict__ b2,
                float* __restrict__ out) {
    __shared__ float row[3 * NCOLS];     // [u | mean_h | mean_g]
    __shared__ float part[8][NCOLS];
    __shared__ float hrow[NCOLS];

    const int b  = blockIdx.x;
    const int t  = threadIdx.x;
    const int oc = t & (NCOLS - 1);
    const int sl = t >> 7;               // 0..7

    if (t < NCOLS) {
        const int ch = g_cnts[0][b];
        const int cg = g_cnts[1][b];
        const float inv_ch = 1.0f / (float)(ch > 1 ? ch : 1);
        const float inv_cg = 1.0f / (float)(cg > 1 ? cg : 1);

        const float sh = g_sums[0][b * NCOLS + t];
        const float sg = g_sums[1][b * NCOLS + t];

        // Re-zero consumed scratch for the next launch/replay.
        g_sums[0][b * NCOLS + t] = 0.0f;
        g_sums[1][b * NCOLS + t] = 0.0f;
        if (t == 0) { g_cnts[0][b] = 0; g_cnts[1][b] = 0; }

        row[t]             = u[b * NCOLS + t];
        row[NCOLS + t]     = sh * inv_ch;
        row[2 * NCOLS + t] = sg * inv_cg;
    }
    __syncthreads();

    // Phase 1: h = leaky_relu(row @ W1 + b1); k split 8 x 48.
    {
        float a0 = 0.f, a1 = 0.f;        // dual accumulators: break fma chain
        const int k0 = sl * 48;
        #pragma unroll 8
        for (int k = 0; k < 48; k += 2) {
            a0 = fmaf(row[k0 + k],     W1[(k0 + k)     * NCOLS + oc], a0);
            a1 = fmaf(row[k0 + k + 1], W1[(k0 + k + 1) * NCOLS + oc], a1);
        }
        part[sl][oc] = a0 + a1;
    }
    __syncthreads();
    if (t < NCOLS) {
        float a = ((part[0][t] + part[1][t]) + (part[2][t] + part[3][t]))
                + ((part[4][t] + part[5][t]) + (part[6][t] + part[7][t]))
                + b1[t];
        hrow[t] = (a > 0.f) ? a : 0.1f * a;   // leaky_relu, slope 0.1
    }
    __syncthreads();

    // Phase 2: out = hrow @ W2 + b2; k split 8 x 16.
    {
        float a0 = 0.f, a1 = 0.f;
        const int k1 = sl * 16;
        #pragma unroll 8
        for (int k = 0; k < 16; k += 2) {
            a0 = fmaf(hrow[k1 + k],     W2[(k1 + k)     * NCOLS + oc], a0);
            a1 = fmaf(hrow[k1 + k + 1], W2[(k1 + k + 1) * NCOLS + oc], a1);
        }
        part[sl][oc] = a0 + a1;
    }
    __syncthreads();
    if (t < NCOLS)
        out[b * NCOLS + t] = ((part[0][t] + part[1][t]) + (part[2][t] + part[3][t]))
                           + ((part[4][t] + part[5][t]) + (part[6][t] + part[7][t]))
                           + b2[t];
}

// ---------------------------------------------------------------------------
// kernel_launch
// Input order: 0 x_h, 1 x_g, 2 edge_index (unused), 3 edge_attr (unused),
//              4 u, 5 batch_h, 6 batch_g, 7 W1, 8 b1, 9 W2, 10 b2.
// ---------------------------------------------------------------------------
extern "C" void kernel_launch(void* const* d_in, const int* in_sizes, int n_in,
                              void* d_out, int out_size) {
    const float* x_h     = (const float*)d_in[0];
    const float* x_g     = (const float*)d_in[1];
    const float* u       = (const float*)d_in[4];
    const int*   batch_h = (const int*)d_in[5];
    const int*   batch_g = (const int*)d_in[6];
    const float* W1      = (const float*)d_in[7];
    const float* b1      = (const float*)d_in[8];
    const float* W2      = (const float*)d_in[9];
    const float* b2      = (const float*)d_in[10];
    float*       out     = (float*)d_out;

    const int n_h = in_sizes[0] / NCOLS;
    const int n_g = in_sizes[1] / NCOLS;
    const int B   = out_size / NCOLS;   // 64

    const int gb_h = (n_h + ROWS_PER_BLOCK - 1) / ROWS_PER_BLOCK;
    const int gb_g = (n_g + ROWS_PER_BLOCK - 1) / ROWS_PER_BLOCK;
    scatter_sum_fused_kernel<<<gb_h + gb_g + 1, SCATTER_THREADS>>>(
        x_h, batch_h, n_h, gb_h, x_g, batch_g, n_g, W1, W2, u);

    finalize_kernel<<<B, FIN_THREADS>>>(u, W1, b1, W2, b2, out);
}